// round 5
// baseline (speedup 1.0000x reference)
#include <cuda_runtime.h>
#include <cstdint>

#define N_NODES 100000
#define N_EDGES 1600000
#define HID 64

#define SCAN_BLK 1024
#define N_SCAN_BLOCKS ((N_NODES + SCAN_BLK - 1) / SCAN_BLK)   // 98

// ---- device-global scratch (no allocations allowed) ----
__device__ float g_xw[(size_t)N_NODES * HID];   // x @ W per layer (25.6 MB)
__device__ int   g_deg[N_NODES];                // in-degree counts / cursors
__device__ int   g_off[N_NODES + 1];            // CSR row offsets (by dst)
__device__ int   g_col[N_EDGES];                // CSR column = src node per slot
__device__ int   g_part[N_SCAN_BLOCKS];         // per-block partial sums
__device__ int   g_idx_is64;                    // edge_index dtype flag

// ---------------------------------------------------------------------------
// zero degree counters + detect edge-index dtype (fused; block 0 detects)
// ---------------------------------------------------------------------------
__global__ __launch_bounds__(256) void zero_deg_detect(const int* __restrict__ ei_raw) {
    int i = blockIdx.x * 256 + threadIdx.x;
    if (i < N_NODES) g_deg[i] = 0;
    if (blockIdx.x == 0 && threadIdx.x == 0) {
        int is64 = 1;
        for (int j = 0; j < 256; j++) {
            int lo = ei_raw[2 * j];
            int hi = ei_raw[2 * j + 1];
            if (hi != 0 || (unsigned)lo >= (unsigned)N_NODES) { is64 = 0; break; }
        }
        g_idx_is64 = is64;
    }
}

__device__ __forceinline__ int load_idx(const int* __restrict__ ei, size_t pos) {
    return g_idx_is64 ? __ldg(&ei[2 * pos]) : __ldg(&ei[pos]);
}

// ---------------------------------------------------------------------------
// CSR build
// ---------------------------------------------------------------------------
__global__ __launch_bounds__(256) void count_deg(const int* __restrict__ ei) {
    int e = blockIdx.x * 256 + threadIdx.x;
    if (e < N_EDGES) {
        int dst = load_idx(ei, (size_t)N_EDGES + e);
        atomicAdd(&g_deg[dst], 1);
    }
}

// A) per-block exclusive scan; block total -> g_part[b]
__global__ __launch_bounds__(SCAN_BLK) void scan_blocks() {
    __shared__ int warpsums[32];
    const int tid = threadIdx.x, lane = tid & 31, wid = tid >> 5;
    const int i = blockIdx.x * SCAN_BLK + tid;

    int v = (i < N_NODES) ? g_deg[i] : 0;
    int s = v;
    #pragma unroll
    for (int d = 1; d < 32; d <<= 1) {
        int t = __shfl_up_sync(0xffffffffu, s, d);
        if (lane >= d) s += t;
    }
    if (lane == 31) warpsums[wid] = s;
    __syncthreads();
    if (wid == 0) {
        int ws = warpsums[lane];
        #pragma unroll
        for (int d = 1; d < 32; d <<= 1) {
            int t = __shfl_up_sync(0xffffffffu, ws, d);
            if (lane >= d) ws += t;
        }
        warpsums[lane] = ws;
    }
    __syncthreads();
    int warpoff = (wid == 0) ? 0 : warpsums[wid - 1];
    if (i < N_NODES) g_off[i] = warpoff + s - v;
    if (tid == SCAN_BLK - 1) g_part[blockIdx.x] = warpsums[31];
}

// B) scan the 98 partials
__global__ __launch_bounds__(128) void scan_partials() {
    __shared__ int warpsums[4];
    const int tid = threadIdx.x, lane = tid & 31, wid = tid >> 5;
    int v = (tid < N_SCAN_BLOCKS) ? g_part[tid] : 0;
    int s = v;
    #pragma unroll
    for (int d = 1; d < 32; d <<= 1) {
        int t = __shfl_up_sync(0xffffffffu, s, d);
        if (lane >= d) s += t;
    }
    if (lane == 31) warpsums[wid] = s;
    __syncthreads();
    int woff = 0;
    for (int w = 0; w < wid; w++) woff += warpsums[w];
    if (tid < N_SCAN_BLOCKS) g_part[tid] = woff + s - v;
    if (tid == 127) g_off[N_NODES] = woff + s;
}

// C) add block offsets; reset g_deg as fill cursor
__global__ __launch_bounds__(SCAN_BLK) void scan_finish() {
    int i = blockIdx.x * SCAN_BLK + threadIdx.x;
    if (i < N_NODES) {
        g_off[i] += g_part[blockIdx.x];
        g_deg[i] = 0;
    }
}

__global__ __launch_bounds__(256) void fill_csr(const int* __restrict__ ei) {
    int e = blockIdx.x * 256 + threadIdx.x;
    if (e < N_EDGES) {
        int src = load_idx(ei, (size_t)e);
        int dst = load_idx(ei, (size_t)N_EDGES + e);
        int slot = g_off[dst] + atomicAdd(&g_deg[dst], 1);
        g_col[slot] = src;
    }
}

// ---------------------------------------------------------------------------
// GEMM: Y[n, 0..63] = X[n, 0..K-1] @ W[K, 64]
// 128x64 block tile, 128 threads, 8x8 per thread, k-chunk 32.
// X staged transposed (sXt[k][row], padded) so all inner loads are LDS.128.
// 64 B LDS per 64 FMA per thread-k => FMA-bound.
// ---------------------------------------------------------------------------
template <int K>
__global__ __launch_bounds__(128) void gemm_f(const float* __restrict__ X,
                                              const float* __restrict__ W,
                                              float* __restrict__ Y,
                                              int nrows) {
    __shared__ float sW[32][64];       // 8 KB
    __shared__ float sXt[32][136];     // 17 KB, padded (136*4 % 16 == 0)

    const int tid  = threadIdx.x;
    const int colg = tid & 7;          // 0..7  -> cols colg*8 .. +7
    const int rowg = tid >> 3;         // 0..15 -> rows rowg*8 .. +7
    const int row0 = blockIdx.x * 128;

    float acc[8][8] = {};

    for (int kc = 0; kc < K; kc += 32) {
        __syncthreads();
        // stage W chunk [32][64]: 512 float4, 4 per thread, coalesced
        #pragma unroll
        for (int j = 0; j < 4; j++) {
            int i4 = (j * 128 + tid) * 4;      // float index, 16B-aligned
            int r = i4 >> 6, c = i4 & 63;
            *(float4*)&sW[r][c] = *(const float4*)&W[(size_t)(kc + r) * 64 + c];
        }
        // stage X chunk transposed: rows row0..+127, k kc..kc+31
        #pragma unroll
        for (int j = 0; j < 8; j++) {
            int r  = j * 16 + (tid >> 3);       // 0..127
            int k4 = (tid & 7) * 4;
            int grow = row0 + r;
            float4 v = (grow < nrows)
                     ? *(const float4*)&X[(size_t)grow * K + kc + k4]
                     : make_float4(0.f, 0.f, 0.f, 0.f);
            sXt[k4 + 0][r] = v.x;
            sXt[k4 + 1][r] = v.y;
            sXt[k4 + 2][r] = v.z;
            sXt[k4 + 3][r] = v.w;
        }
        __syncthreads();

        #pragma unroll
        for (int k = 0; k < 32; k++) {
            float xv[8], wv[8];
            *(float4*)&xv[0] = *(float4*)&sXt[k][rowg * 8];
            *(float4*)&xv[4] = *(float4*)&sXt[k][rowg * 8 + 4];
            *(float4*)&wv[0] = *(float4*)&sW[k][colg * 8];
            *(float4*)&wv[4] = *(float4*)&sW[k][colg * 8 + 4];
            #pragma unroll
            for (int r = 0; r < 8; r++)
                #pragma unroll
                for (int c = 0; c < 8; c++)
                    acc[r][c] = fmaf(xv[r], wv[c], acc[r][c]);
        }
    }

    #pragma unroll
    for (int r = 0; r < 8; r++) {
        int grow = row0 + rowg * 8 + r;
        if (grow < nrows) {
            *(float4*)&Y[(size_t)grow * 64 + colg * 8]     = *(float4*)&acc[r][0];
            *(float4*)&Y[(size_t)grow * 64 + colg * 8 + 4] = *(float4*)&acc[r][4];
        }
    }
}

// ---------------------------------------------------------------------------
// CSR gather-aggregate: out[n,:] = sum_{e in in(n)} xw[col[e],:] + b
// One warp per node; half-warps alternate edges; lane owns a float4.
// Index loads software-pipelined one iteration ahead.
// ---------------------------------------------------------------------------
__global__ __launch_bounds__(256) void gather64(const float* __restrict__ xw,
                                                float* __restrict__ out,
                                                const float* __restrict__ b) {
    int warp_id = (blockIdx.x * 256 + threadIdx.x) >> 5;
    if (warp_id >= N_NODES) return;
    const int lane = threadIdx.x & 31;
    const int half = lane >> 4;
    const int q    = lane & 15;

    const int beg = __ldg(&g_off[warp_id]);
    const int end = __ldg(&g_off[warp_id + 1]);

    float4 acc = make_float4(0.f, 0.f, 0.f, 0.f);
    int i = beg + half;
    int nxt = (i < end) ? __ldg(&g_col[i]) : 0;
    while (i < end) {
        int src = nxt;
        int j = i + 2;
        if (j < end) nxt = __ldg(&g_col[j]);
        float4 v = *reinterpret_cast<const float4*>(xw + (size_t)src * 64 + q * 4);
        acc.x += v.x; acc.y += v.y; acc.z += v.z; acc.w += v.w;
        i = j;
    }
    acc.x += __shfl_xor_sync(0xffffffffu, acc.x, 16);
    acc.y += __shfl_xor_sync(0xffffffffu, acc.y, 16);
    acc.z += __shfl_xor_sync(0xffffffffu, acc.z, 16);
    acc.w += __shfl_xor_sync(0xffffffffu, acc.w, 16);

    if (half == 0) {
        float4 bv = reinterpret_cast<const float4*>(b)[q];
        acc.x += bv.x; acc.y += bv.y; acc.z += bv.z; acc.w += bv.w;
        *reinterpret_cast<float4*>(out + (size_t)warp_id * 64 + q * 4) = acc;
    }
}

// ---------------------------------------------------------------------------
extern "C" void kernel_launch(void* const* d_in, const int* in_sizes, int n_in,
                              void* d_out, int out_size) {
    const float* x  = (const float*)d_in[0];
    const int*   ei = (const int*)d_in[1];
    const float* W1 = (const float*)d_in[2];
    const float* b1 = (const float*)d_in[3];
    const float* W2 = (const float*)d_in[4];
    const float* b2 = (const float*)d_in[5];
    const float* W3 = (const float*)d_in[6];
    const float* b3 = (const float*)d_in[7];

    float* h1 = (float*)d_out;
    float* h2 = h1 + (size_t)N_NODES * HID;
    float* h3 = h2 + (size_t)N_NODES * HID;

    float* xw;
    cudaGetSymbolAddress((void**)&xw, g_xw);

    const int ggrid = (N_NODES + 127) / 128;
    const int egrid = (N_EDGES + 255) / 256;
    const int ngrid = (N_NODES + 255) / 256;
    const int agrid = (N_NODES * 32 + 255) / 256;

    // --- CSR build ---
    zero_deg_detect<<<ngrid, 256>>>(ei);
    count_deg<<<egrid, 256>>>(ei);
    scan_blocks<<<N_SCAN_BLOCKS, SCAN_BLK>>>();
    scan_partials<<<1, 128>>>();
    scan_finish<<<N_SCAN_BLOCKS, SCAN_BLK>>>();
    fill_csr<<<egrid, 256>>>(ei);

    // --- Layer 1 ---
    gemm_f<128><<<ggrid, 128>>>(x, W1, xw, N_NODES);
    gather64<<<agrid, 256>>>(xw, h1, b1);
    // --- Layer 2 ---
    gemm_f<64><<<ggrid, 128>>>(h1, W2, xw, N_NODES);
    gather64<<<agrid, 256>>>(xw, h2, b2);
    // --- Layer 3 ---
    gemm_f<64><<<ggrid, 128>>>(h2, W3, xw, N_NODES);
    gather64<<<agrid, 256>>>(xw, h3, b3);
}

// round 6
// speedup vs baseline: 1.0868x; 1.0868x over previous
#include <cuda_runtime.h>
#include <cstdint>

#define N_NODES 100000
#define N_EDGES 1600000
#define HID 64

#define SCAN_BLK 1024
#define N_SCAN_BLOCKS ((N_NODES + SCAN_BLK - 1) / SCAN_BLK)   // 98

// ---- device-global scratch (no allocations allowed) ----
__device__ float g_xw[(size_t)N_NODES * HID];   // x @ W per layer (25.6 MB)
__device__ int   g_deg[N_NODES];                // in-degree counts / cursors
__device__ int   g_off[N_NODES + 1];            // CSR row offsets (by dst)
__device__ int   g_col[N_EDGES];                // CSR column = src node per slot
__device__ int   g_part[N_SCAN_BLOCKS];         // per-block partial sums
__device__ int   g_idx_is64;                    // edge_index dtype flag

// ---------------------------------------------------------------------------
// zero degree counters + detect edge-index dtype (fused; block 0 detects)
// ---------------------------------------------------------------------------
__global__ __launch_bounds__(256) void zero_deg_detect(const int* __restrict__ ei_raw) {
    int i = blockIdx.x * 256 + threadIdx.x;
    if (i < N_NODES) g_deg[i] = 0;
    if (blockIdx.x == 0 && threadIdx.x == 0) {
        int is64 = 1;
        for (int j = 0; j < 256; j++) {
            int lo = ei_raw[2 * j];
            int hi = ei_raw[2 * j + 1];
            if (hi != 0 || (unsigned)lo >= (unsigned)N_NODES) { is64 = 0; break; }
        }
        g_idx_is64 = is64;
    }
}

__device__ __forceinline__ int load_idx(const int* __restrict__ ei, size_t pos) {
    return g_idx_is64 ? __ldg(&ei[2 * pos]) : __ldg(&ei[pos]);
}

// ---------------------------------------------------------------------------
// CSR build
// ---------------------------------------------------------------------------
__global__ __launch_bounds__(256) void count_deg(const int* __restrict__ ei) {
    int e = blockIdx.x * 256 + threadIdx.x;
    if (e < N_EDGES) {
        int dst = load_idx(ei, (size_t)N_EDGES + e);
        atomicAdd(&g_deg[dst], 1);
    }
}

// A) per-block exclusive scan; block total -> g_part[b]
__global__ __launch_bounds__(SCAN_BLK) void scan_blocks() {
    __shared__ int warpsums[32];
    const int tid = threadIdx.x, lane = tid & 31, wid = tid >> 5;
    const int i = blockIdx.x * SCAN_BLK + tid;

    int v = (i < N_NODES) ? g_deg[i] : 0;
    int s = v;
    #pragma unroll
    for (int d = 1; d < 32; d <<= 1) {
        int t = __shfl_up_sync(0xffffffffu, s, d);
        if (lane >= d) s += t;
    }
    if (lane == 31) warpsums[wid] = s;
    __syncthreads();
    if (wid == 0) {
        int ws = warpsums[lane];
        #pragma unroll
        for (int d = 1; d < 32; d <<= 1) {
            int t = __shfl_up_sync(0xffffffffu, ws, d);
            if (lane >= d) ws += t;
        }
        warpsums[lane] = ws;
    }
    __syncthreads();
    int warpoff = (wid == 0) ? 0 : warpsums[wid - 1];
    if (i < N_NODES) g_off[i] = warpoff + s - v;
    if (tid == SCAN_BLK - 1) g_part[blockIdx.x] = warpsums[31];
}

// B+C fused) each block sums g_part[0..blockIdx) itself, adds, resets cursors
__global__ __launch_bounds__(SCAN_BLK) void scan_finish() {
    __shared__ int soff;
    const int tid = threadIdx.x;
    if (tid < 32) {
        int sum = 0;
        for (int j = tid; j < blockIdx.x; j += 32) sum += g_part[j];
        #pragma unroll
        for (int d = 16; d > 0; d >>= 1)
            sum += __shfl_xor_sync(0xffffffffu, sum, d);
        if (tid == 0) soff = sum;
    }
    __syncthreads();
    int off = soff;
    int i = blockIdx.x * SCAN_BLK + tid;
    if (i < N_NODES) {
        g_off[i] += off;
        g_deg[i] = 0;
    }
    if (blockIdx.x == N_SCAN_BLOCKS - 1 && tid == 0)
        g_off[N_NODES] = off + g_part[N_SCAN_BLOCKS - 1];
}

__global__ __launch_bounds__(256) void fill_csr(const int* __restrict__ ei) {
    int e = blockIdx.x * 256 + threadIdx.x;
    if (e < N_EDGES) {
        int src = load_idx(ei, (size_t)e);
        int dst = load_idx(ei, (size_t)N_EDGES + e);
        int slot = g_off[dst] + atomicAdd(&g_deg[dst], 1);
        g_col[slot] = src;
    }
}

// ---------------------------------------------------------------------------
// GEMM: Y[n, 0..63] = X[n, 0..K-1] @ W[K, 64]
// 128x64 block tile, 128 threads, 8x8 per thread, k-chunk 32, transposed X.
// ---------------------------------------------------------------------------
template <int K>
__global__ __launch_bounds__(128) void gemm_f(const float* __restrict__ X,
                                              const float* __restrict__ W,
                                              float* __restrict__ Y,
                                              int nrows) {
    __shared__ float sW[32][64];
    __shared__ float sXt[32][136];

    const int tid  = threadIdx.x;
    const int colg = tid & 7;
    const int rowg = tid >> 3;
    const int row0 = blockIdx.x * 128;

    float acc[8][8] = {};

    for (int kc = 0; kc < K; kc += 32) {
        __syncthreads();
        #pragma unroll
        for (int j = 0; j < 4; j++) {
            int i4 = (j * 128 + tid) * 4;
            int r = i4 >> 6, c = i4 & 63;
            *(float4*)&sW[r][c] = *(const float4*)&W[(size_t)(kc + r) * 64 + c];
        }
        #pragma unroll
        for (int j = 0; j < 8; j++) {
            int r  = j * 16 + (tid >> 3);
            int k4 = (tid & 7) * 4;
            int grow = row0 + r;
            float4 v = (grow < nrows)
                     ? *(const float4*)&X[(size_t)grow * K + kc + k4]
                     : make_float4(0.f, 0.f, 0.f, 0.f);
            sXt[k4 + 0][r] = v.x;
            sXt[k4 + 1][r] = v.y;
            sXt[k4 + 2][r] = v.z;
            sXt[k4 + 3][r] = v.w;
        }
        __syncthreads();

        #pragma unroll
        for (int k = 0; k < 32; k++) {
            float xv[8], wv[8];
            *(float4*)&xv[0] = *(float4*)&sXt[k][rowg * 8];
            *(float4*)&xv[4] = *(float4*)&sXt[k][rowg * 8 + 4];
            *(float4*)&wv[0] = *(float4*)&sW[k][colg * 8];
            *(float4*)&wv[4] = *(float4*)&sW[k][colg * 8 + 4];
            #pragma unroll
            for (int r = 0; r < 8; r++)
                #pragma unroll
                for (int c = 0; c < 8; c++)
                    acc[r][c] = fmaf(xv[r], wv[c], acc[r][c]);
        }
    }

    #pragma unroll
    for (int r = 0; r < 8; r++) {
        int grow = row0 + rowg * 8 + r;
        if (grow < nrows) {
            *(float4*)&Y[(size_t)grow * 64 + colg * 8]     = *(float4*)&acc[r][0];
            *(float4*)&Y[(size_t)grow * 64 + colg * 8 + 4] = *(float4*)&acc[r][4];
        }
    }
}

// ---------------------------------------------------------------------------
// CSR gather-aggregate: out[n,:] = sum_{e in in(n)} xw[col[e],:] + b
// ---------------------------------------------------------------------------
__global__ __launch_bounds__(256) void gather64(const float* __restrict__ xw,
                                                float* __restrict__ out,
                                                const float* __restrict__ b) {
    int warp_id = (blockIdx.x * 256 + threadIdx.x) >> 5;
    if (warp_id >= N_NODES) return;
    const int lane = threadIdx.x & 31;
    const int half = lane >> 4;
    const int q    = lane & 15;

    const int beg = __ldg(&g_off[warp_id]);
    const int end = __ldg(&g_off[warp_id + 1]);

    float4 acc = make_float4(0.f, 0.f, 0.f, 0.f);
    int i = beg + half;
    int nxt = (i < end) ? __ldg(&g_col[i]) : 0;
    while (i < end) {
        int src = nxt;
        int j = i + 2;
        if (j < end) nxt = __ldg(&g_col[j]);
        float4 v = *reinterpret_cast<const float4*>(xw + (size_t)src * 64 + q * 4);
        acc.x += v.x; acc.y += v.y; acc.z += v.z; acc.w += v.w;
        i = j;
    }
    acc.x += __shfl_xor_sync(0xffffffffu, acc.x, 16);
    acc.y += __shfl_xor_sync(0xffffffffu, acc.y, 16);
    acc.z += __shfl_xor_sync(0xffffffffu, acc.z, 16);
    acc.w += __shfl_xor_sync(0xffffffffu, acc.w, 16);

    if (half == 0) {
        float4 bv = reinterpret_cast<const float4*>(b)[q];
        acc.x += bv.x; acc.y += bv.y; acc.z += bv.z; acc.w += bv.w;
        *reinterpret_cast<float4*>(out + (size_t)warp_id * 64 + q * 4) = acc;
    }
}

// ---------------------------------------------------------------------------
extern "C" void kernel_launch(void* const* d_in, const int* in_sizes, int n_in,
                              void* d_out, int out_size) {
    const float* x  = (const float*)d_in[0];
    const int*   ei = (const int*)d_in[1];
    const float* W1 = (const float*)d_in[2];
    const float* b1 = (const float*)d_in[3];
    const float* W2 = (const float*)d_in[4];
    const float* b2 = (const float*)d_in[5];
    const float* W3 = (const float*)d_in[6];
    const float* b3 = (const float*)d_in[7];

    float* h1 = (float*)d_out;
    float* h2 = h1 + (size_t)N_NODES * HID;
    float* h3 = h2 + (size_t)N_NODES * HID;

    float* xw;
    cudaGetSymbolAddress((void**)&xw, g_xw);

    const int ggrid = (N_NODES + 127) / 128;
    const int egrid = (N_EDGES + 255) / 256;
    const int ngrid = (N_NODES + 255) / 256;
    const int agrid = (N_NODES * 32 + 255) / 256;

    // Host-side resources created once (no device memory involved).
    static cudaStream_t s_csr = nullptr;
    static cudaEvent_t  ev_fork = nullptr, ev_join = nullptr;
    if (s_csr == nullptr) {
        cudaStreamCreateWithFlags(&s_csr, cudaStreamNonBlocking);
        cudaEventCreateWithFlags(&ev_fork, cudaEventDisableTiming);
        cudaEventCreateWithFlags(&ev_join, cudaEventDisableTiming);
    }

    // --- Fork: CSR build on side stream, GEMM1 on main stream, concurrently ---
    cudaEventRecord(ev_fork, 0);
    cudaStreamWaitEvent(s_csr, ev_fork, 0);

    zero_deg_detect<<<ngrid, 256, 0, s_csr>>>(ei);
    count_deg<<<egrid, 256, 0, s_csr>>>(ei);
    scan_blocks<<<N_SCAN_BLOCKS, SCAN_BLK, 0, s_csr>>>();
    scan_finish<<<N_SCAN_BLOCKS, SCAN_BLK, 0, s_csr>>>();
    fill_csr<<<egrid, 256, 0, s_csr>>>(ei);
    cudaEventRecord(ev_join, s_csr);

    gemm_f<128><<<ggrid, 128>>>(x, W1, xw, N_NODES);      // main stream, overlapped

    // --- Join: gather1 needs both CSR and xw ---
    cudaStreamWaitEvent(0, ev_join, 0);

    gather64<<<agrid, 256>>>(xw, h1, b1);
    gemm_f<64><<<ggrid, 128>>>(h1, W2, xw, N_NODES);
    gather64<<<agrid, 256>>>(xw, h2, b2);
    gemm_f<64><<<ggrid, 128>>>(h2, W3, xw, N_NODES);
    gather64<<<agrid, 256>>>(xw, h3, b3);
}